// round 4
// baseline (speedup 1.0000x reference)
#include <cuda_runtime.h>
#include <cstdint>

// out[src[e]*F + k] += attrs[k*E + e]   (attrs buffer is feature-major (F,E))
// attr_idx is int32 (JAX x64 disabled downcasts the declared int64).

__global__ void scatter_sum_f16_kernel(const float* __restrict__ attrs,
                                       const int* __restrict__ src,
                                       float* __restrict__ out,
                                       int E, int out_size)
{
    int e = blockIdx.x * blockDim.x + threadIdx.x;
    if (e >= E) return;
    int n = src[e];                       // row 0 of attr_idx = src node
    long long base = (long long)n * 16;
    if (n < 0 || base + 16 > out_size) return;   // defensive: never OOB
    float* o = out + base;
    #pragma unroll
    for (int k = 0; k < 16; k++) {
        // attrs[k*E + e] is coalesced across the warp for every k
        atomicAdd(o + k, __ldg(attrs + (size_t)k * E + e));
    }
}

__global__ void scatter_sum_generic_kernel(const float* __restrict__ attrs,
                                           const int* __restrict__ src,
                                           float* __restrict__ out,
                                           int E, int F, int out_size)
{
    int e = blockIdx.x * blockDim.x + threadIdx.x;
    if (e >= E) return;
    int n = src[e];
    long long base = (long long)n * F;
    if (n < 0 || base + F > out_size) return;
    float* o = out + base;
    for (int k = 0; k < F; k++) {
        atomicAdd(o + k, __ldg(attrs + (size_t)k * E + e));
    }
}

extern "C" void kernel_launch(void* const* d_in, const int* in_sizes, int n_in,
                              void* d_out, int out_size)
{
    const float* attrs = (const float*)d_in[0];   // (E, F) buffer, used as (F, E)
    const int*   aidx  = (const int*)d_in[1];     // (2, E) int32; row 0 = src

    int E = in_sizes[1] / 2;
    int F = in_sizes[0] / E;

    float* out = (float*)d_out;

    // Output is poisoned; zero it (memset node is graph-capturable).
    cudaMemsetAsync(d_out, 0, (size_t)out_size * sizeof(float), 0);

    const int threads = 256;
    int blocks = (E + threads - 1) / threads;

    if (F == 16) {
        scatter_sum_f16_kernel<<<blocks, threads, 0, 0>>>(attrs, aidx, out, E, out_size);
    } else {
        scatter_sum_generic_kernel<<<blocks, threads, 0, 0>>>(attrs, aidx, out, E, F, out_size);
    }
}

// round 5
// speedup vs baseline: 2.5256x; 2.5256x over previous
#include <cuda_runtime.h>
#include <cstdint>

// out[src[e]*16 + k] += attrs[k*E + e]   (attrs buffer is feature-major (F,E))
// attr_idx is int32. L2-atomic-op bound => use red.global.add.v4.f32
// (sm_90+) to carry 16B per LTS op: 64M scalar REDs -> 16M v4 REDs.

__device__ __forceinline__ void red_add_v4(float* addr, float a, float b, float c, float d)
{
    asm volatile("red.global.add.v4.f32 [%0], {%1, %2, %3, %4};"
                 :: "l"(addr), "f"(a), "f"(b), "f"(c), "f"(d)
                 : "memory");
}

__global__ void scatter_sum_f16_kernel(const float* __restrict__ attrs,
                                       const int* __restrict__ src,
                                       float* __restrict__ out,
                                       int E, int out_size)
{
    int e = blockIdx.x * blockDim.x + threadIdx.x;
    if (e >= E) return;
    int n = src[e];                        // row 0 of attr_idx = src node
    long long base = (long long)n * 16;
    if (n < 0 || base + 16 > out_size) return;   // defensive: never OOB

    // Gather all 16 feature values first (each load coalesced across the warp).
    float v[16];
    #pragma unroll
    for (int k = 0; k < 16; k++)
        v[k] = __ldg(attrs + (size_t)k * E + e);

    float* o = out + base;                 // 64B-aligned (n*16 floats)
    red_add_v4(o + 0,  v[0],  v[1],  v[2],  v[3]);
    red_add_v4(o + 4,  v[4],  v[5],  v[6],  v[7]);
    red_add_v4(o + 8,  v[8],  v[9],  v[10], v[11]);
    red_add_v4(o + 12, v[12], v[13], v[14], v[15]);
}

__global__ void scatter_sum_generic_kernel(const float* __restrict__ attrs,
                                           const int* __restrict__ src,
                                           float* __restrict__ out,
                                           int E, int F, int out_size)
{
    int e = blockIdx.x * blockDim.x + threadIdx.x;
    if (e >= E) return;
    int n = src[e];
    long long base = (long long)n * F;
    if (n < 0 || base + F > out_size) return;
    float* o = out + base;
    for (int k = 0; k < F; k++)
        atomicAdd(o + k, __ldg(attrs + (size_t)k * E + e));
}

extern "C" void kernel_launch(void* const* d_in, const int* in_sizes, int n_in,
                              void* d_out, int out_size)
{
    const float* attrs = (const float*)d_in[0];   // (E, F) buffer, used as (F, E)
    const int*   aidx  = (const int*)d_in[1];     // (2, E) int32; row 0 = src

    int E = in_sizes[1] / 2;
    int F = in_sizes[0] / E;

    float* out = (float*)d_out;

    // Output is poisoned; zero it (memset node is graph-capturable).
    cudaMemsetAsync(d_out, 0, (size_t)out_size * sizeof(float), 0);

    const int threads = 256;
    int blocks = (E + threads - 1) / threads;

    if (F == 16) {
        scatter_sum_f16_kernel<<<blocks, threads, 0, 0>>>(attrs, aidx, out, E, out_size);
    } else {
        scatter_sum_generic_kernel<<<blocks, threads, 0, 0>>>(attrs, aidx, out, E, F, out_size);
    }
}

// round 10
// speedup vs baseline: 2.9630x; 1.1732x over previous
#include <cuda_runtime.h>
#include <cstdint>

// out[src[e]*16 + k] += attrs[k*E + e]   (attrs is feature-major (F,E); attr_idx int32)
// Bound by L2/L1 atomic lane throughput (16M RED.v4 lanes). This version trims the
// load side: 4 consecutive edges per thread -> LDG.128 attr loads + int4 index load,
// features processed in two halves of 8 to cap live registers.

__device__ __forceinline__ void red_add_v4(float* addr, float a, float b, float c, float d)
{
    asm volatile("red.global.add.v4.f32 [%0], {%1, %2, %3, %4};"
                 :: "l"(addr), "f"(a), "f"(b), "f"(c), "f"(d)
                 : "memory");
}

// Eq = E/4 (number of edge quads). attrs4 laid out as (16, Eq) float4.
__global__ void scatter_sum_f16_q4(const float4* __restrict__ attrs4,
                                   const int4* __restrict__ src4,
                                   float* __restrict__ out,
                                   int Eq, int out_size)
{
    int q = blockIdx.x * blockDim.x + threadIdx.x;
    if (q >= Eq) return;

    int4 n4 = __ldg(src4 + q);            // 4 consecutive src node ids

    // Per-edge output bases (guarded; invalid -> nullptr, RED skipped)
    float* o0 = ((unsigned)n4.x * 16u + 16u <= (unsigned)out_size) ? out + (size_t)n4.x * 16 : nullptr;
    float* o1 = ((unsigned)n4.y * 16u + 16u <= (unsigned)out_size) ? out + (size_t)n4.y * 16 : nullptr;
    float* o2 = ((unsigned)n4.z * 16u + 16u <= (unsigned)out_size) ? out + (size_t)n4.z * 16 : nullptr;
    float* o3 = ((unsigned)n4.w * 16u + 16u <= (unsigned)out_size) ? out + (size_t)n4.w * 16 : nullptr;

    // ---- features 0..7 ----
    {
        float4 v[8];
        #pragma unroll
        for (int k = 0; k < 8; k++)
            v[k] = __ldg(attrs4 + (size_t)k * Eq + q);   // coalesced 512B/warp per k

        if (o0) { red_add_v4(o0 + 0, v[0].x, v[1].x, v[2].x, v[3].x);
                  red_add_v4(o0 + 4, v[4].x, v[5].x, v[6].x, v[7].x); }
        if (o1) { red_add_v4(o1 + 0, v[0].y, v[1].y, v[2].y, v[3].y);
                  red_add_v4(o1 + 4, v[4].y, v[5].y, v[6].y, v[7].y); }
        if (o2) { red_add_v4(o2 + 0, v[0].z, v[1].z, v[2].z, v[3].z);
                  red_add_v4(o2 + 4, v[4].z, v[5].z, v[6].z, v[7].z); }
        if (o3) { red_add_v4(o3 + 0, v[0].w, v[1].w, v[2].w, v[3].w);
                  red_add_v4(o3 + 4, v[4].w, v[5].w, v[6].w, v[7].w); }
    }
    // ---- features 8..15 ----
    {
        float4 v[8];
        #pragma unroll
        for (int k = 0; k < 8; k++)
            v[k] = __ldg(attrs4 + (size_t)(k + 8) * Eq + q);

        if (o0) { red_add_v4(o0 + 8,  v[0].x, v[1].x, v[2].x, v[3].x);
                  red_add_v4(o0 + 12, v[4].x, v[5].x, v[6].x, v[7].x); }
        if (o1) { red_add_v4(o1 + 8,  v[0].y, v[1].y, v[2].y, v[3].y);
                  red_add_v4(o1 + 12, v[4].y, v[5].y, v[6].y, v[7].y); }
        if (o2) { red_add_v4(o2 + 8,  v[0].z, v[1].z, v[2].z, v[3].z);
                  red_add_v4(o2 + 12, v[4].z, v[5].z, v[6].z, v[7].z); }
        if (o3) { red_add_v4(o3 + 8,  v[0].w, v[1].w, v[2].w, v[3].w);
                  red_add_v4(o3 + 12, v[4].w, v[5].w, v[6].w, v[7].w); }
    }
}

// Scalar fallback for edge tail / F != 16.
__global__ void scatter_sum_scalar(const float* __restrict__ attrs,
                                   const int* __restrict__ src,
                                   float* __restrict__ out,
                                   int e0, int E, int F, int out_size)
{
    int e = e0 + blockIdx.x * blockDim.x + threadIdx.x;
    if (e >= E) return;
    int n = src[e];
    long long base = (long long)n * F;
    if (n < 0 || base + F > out_size) return;
    float* o = out + base;
    for (int k = 0; k < F; k++)
        atomicAdd(o + k, __ldg(attrs + (size_t)k * E + e));
}

extern "C" void kernel_launch(void* const* d_in, const int* in_sizes, int n_in,
                              void* d_out, int out_size)
{
    const float* attrs = (const float*)d_in[0];   // (E, F) buffer, used as (F, E)
    const int*   aidx  = (const int*)d_in[1];     // (2, E) int32; row 0 = src

    int E = in_sizes[1] / 2;
    int F = in_sizes[0] / E;

    float* out = (float*)d_out;

    cudaMemsetAsync(d_out, 0, (size_t)out_size * sizeof(float), 0);

    const int threads = 256;

    if (F == 16 && (E % 4) == 0) {
        int Eq = E / 4;
        int blocks = (Eq + threads - 1) / threads;
        scatter_sum_f16_q4<<<blocks, threads, 0, 0>>>(
            (const float4*)attrs, (const int4*)aidx, out, Eq, out_size);
    } else {
        int blocks = (E + threads - 1) / threads;
        scatter_sum_scalar<<<blocks, threads, 0, 0>>>(attrs, aidx, out, 0, E, F, out_size);
    }
}